// round 13
// baseline (speedup 1.0000x reference)
#include <cuda_runtime.h>
#include <cuda_fp16.h>

#define Bx 4
#define Lx 512
#define Dx 128
#define NH 12              // harmonics m = 1,3,...,23
#define KP (NH * 2 * Dx)   // 3072 feature dim
#define NJ 8               // j-tiles (=partials) per (batch, i-tile)
#define LOG2E 1.4426950408889634f
#define OMEGA1 0.22439948f // pi/14

// Scratch (static device arrays: allowed; no allocations anywhere)
__device__ float g_Q[Bx * Lx * Dx];               // q projection (pre-tanh)
__device__ float g_K[Bx * Lx * Dx];
__device__ uint4 g_FQ4[(size_t)Bx * Lx * KP / 8]; // f16 features, 16B aligned
__device__ uint4 g_FK4[(size_t)Bx * Lx * KP / 8];
__device__ float g_acc[NJ][(size_t)Bx * Lx * Dx]; // j-split AV partials (8MB)
__device__ float g_ps[NJ][Bx * Lx];               // j-split row-sum partials

// Fourier sine coefficients of mirrored tanh: b_m = pi / (7 sinh(m pi^2/28))
__device__ __constant__ float c_B[NH] = {
    1.24737f,     0.354585f,   0.158755f,   0.0766902f,
    0.0376905f,   0.0186002f,  0.00918841f, 0.00454012f,
    0.00224348f,  0.00110862f, 0.000547829f, 0.000270714f
};

__device__ __forceinline__ unsigned saddr(const void* p) {
    return (unsigned)__cvta_generic_to_shared(p);
}
__device__ __forceinline__ void cp16(unsigned dst, const void* src) {
    asm volatile("cp.async.cg.shared.global [%0], [%1], 16;" :: "r"(dst), "l"(src));
}
__device__ __forceinline__ void ldsm_x4(unsigned& r0, unsigned& r1, unsigned& r2,
                                        unsigned& r3, unsigned addr) {
    asm volatile("ldmatrix.sync.aligned.m8n8.x4.shared.b16 {%0,%1,%2,%3}, [%4];"
                 : "=r"(r0), "=r"(r1), "=r"(r2), "=r"(r3) : "r"(addr));
}
__device__ __forceinline__ void mma16816(float* c, const unsigned* a,
                                         unsigned b0, unsigned b1) {
    asm volatile(
        "mma.sync.aligned.m16n8k16.row.col.f32.f16.f16.f32 "
        "{%0,%1,%2,%3}, {%4,%5,%6,%7}, {%8,%9}, {%0,%1,%2,%3};"
        : "+f"(c[0]), "+f"(c[1]), "+f"(c[2]), "+f"(c[3])
        : "r"(a[0]), "r"(a[1]), "r"(a[2]), "r"(a[3]), "r"(b0), "r"(b1));
}
__device__ __forceinline__ float ex2_fast(float v) {
    float y;
    asm("ex2.approx.f32 %0, %1;" : "=f"(y) : "f"(v));
    return y;
}

// ---------------------------------------------------------------------------
// Kernel 1: projections q = x Wq^T + bq, k = x Wk^T + bk.
// Register-prefetch pipeline over 32-d chunks.
// ---------------------------------------------------------------------------
__global__ __launch_bounds__(256) void qk_kernel(
        const float* __restrict__ x,
        const float* __restrict__ Wq, const float* __restrict__ bq,
        const float* __restrict__ Wk, const float* __restrict__ bk) {
    __shared__ float Wsh[32][130];
    __shared__ float xsh[32][20];

    int which = blockIdx.y;
    int row0 = blockIdx.x * 16;
    const float* W = which ? Wk : Wq;
    const float* bias = which ? bk : bq;
    float* outp = which ? g_K : g_Q;

    int tid = threadIdx.x;
    int e0 = 2 * (tid & 63);
    int rg = tid >> 6;

    const float4* W4 = (const float4*)W;
    const float4* x4 = (const float4*)(x + (size_t)row0 * Dx);

    float4 wreg[4];
    float4 xreg;
#pragma unroll
    for (int k = 0; k < 4; k++) {
        int idx = tid + 256 * k;
        wreg[k] = W4[(size_t)(idx >> 3) * 32 + (idx & 7)];
    }
    if (tid < 128) xreg = x4[(size_t)(tid >> 3) * 32 + (tid & 7)];

    float acc[4][2];
#pragma unroll
    for (int r = 0; r < 4; r++) { acc[r][0] = 0.f; acc[r][1] = 0.f; }

    for (int c = 0; c < 4; c++) {
        __syncthreads();
#pragma unroll
        for (int k = 0; k < 4; k++) {
            int idx = tid + 256 * k;
            int e = idx >> 3, j4 = idx & 7;
            Wsh[4 * j4 + 0][e] = wreg[k].x;
            Wsh[4 * j4 + 1][e] = wreg[k].y;
            Wsh[4 * j4 + 2][e] = wreg[k].z;
            Wsh[4 * j4 + 3][e] = wreg[k].w;
        }
        if (tid < 128) {
            int r = tid >> 3, j4 = tid & 7;
            xsh[4 * j4 + 0][r] = xreg.x;
            xsh[4 * j4 + 1][r] = xreg.y;
            xsh[4 * j4 + 2][r] = xreg.z;
            xsh[4 * j4 + 3][r] = xreg.w;
        }
        __syncthreads();

        if (c < 3) {
            int dc4n = (c + 1) * 8;
#pragma unroll
            for (int k = 0; k < 4; k++) {
                int idx = tid + 256 * k;
                wreg[k] = W4[(size_t)(idx >> 3) * 32 + dc4n + (idx & 7)];
            }
            if (tid < 128) xreg = x4[(size_t)(tid >> 3) * 32 + dc4n + (tid & 7)];
        }

#pragma unroll
        for (int d = 0; d < 32; d++) {
            float2 wv = *(const float2*)&Wsh[d][e0];
            float4 xv = *(const float4*)&xsh[d][4 * rg];
            acc[0][0] += wv.x * xv.x;  acc[0][1] += wv.y * xv.x;
            acc[1][0] += wv.x * xv.y;  acc[1][1] += wv.y * xv.y;
            acc[2][0] += wv.x * xv.z;  acc[2][1] += wv.y * xv.z;
            acc[3][0] += wv.x * xv.w;  acc[3][1] += wv.y * xv.w;
        }
    }

    float b0 = bias[e0], b1 = bias[e0 + 1];
#pragma unroll
    for (int r = 0; r < 4; r++) {
        int row = row0 + 4 * rg + r;
        *(float2*)&outp[(size_t)row * Dx + e0] =
            make_float2(acc[r][0] + b0, acc[r][1] + b1);
    }
}

// ---------------------------------------------------------------------------
// Kernel 2: Fourier features.
// Q side: FQ[row][h*256 + 2d]   = b_h * w'_d * sin(w_h q),  +1 = ... * cos
// K side: FK[row][h*256 + 2d]   = cos(w_h k),               +1 = sin(w_h k)
// ---------------------------------------------------------------------------
__global__ __launch_bounds__(128) void feat_kernel(const float* __restrict__ w) {
    __shared__ unsigned sbuf[4][NH * Dx];   // [row][h*128+d] half2 words, 24KB

    int which = blockIdx.y;
    int row0 = blockIdx.x * 4;
    const float* P = which ? g_K : g_Q;
    uint4* F4 = which ? g_FK4 : g_FQ4;

    int d = threadIdx.x;
    float wp = w[d] * LOG2E;   // only used on q side

#pragma unroll
    for (int r = 0; r < 4; r++) {
        float z = P[(size_t)(row0 + r) * Dx + d];
        float s1, c1;
        __sincosf(OMEGA1 * z, &s1, &c1);
        float s2 = 2.f * s1 * c1;
        float c2 = fmaf(-2.f * s1, s1, 1.f);
        float sm = s1, cm = c1;
#pragma unroll
        for (int h = 0; h < NH; h++) {
            __half2 hv;
            if (which == 0) {
                float sc = c_B[h] * wp;
                hv = __floats2half2_rn(sc * sm, sc * cm);
            } else {
                hv = __floats2half2_rn(cm, sm);
            }
            sbuf[r][h * Dx + d] = *(unsigned*)&hv;
            float ns = fmaf(sm, c2, cm * s2);
            float nc = fmaf(cm, c2, -sm * s2);
            sm = ns; cm = nc;
        }
    }
    __syncthreads();

    const uint4* sb4 = (const uint4*)sbuf;
    for (int i = threadIdx.x; i < 4 * (KP / 8); i += 128) {
        int r = i / (KP / 8), off = i % (KP / 8);
        F4[(size_t)(row0 + r) * (KP / 8) + off] = sb4[i];
    }
}

// ---------------------------------------------------------------------------
// Kernel 3 (fused): S-tile = FQ @ FK^T (full K, f16 HMMA, f32 accum), then
// IN-KERNEL: p = exp2(S) in registers -> P smem (reuses dead As/Bs region),
// fragment row-sums -> g_ps partial, stage x[j0:j0+64] -> smem, f32 AV
// P @ x -> g_acc partial. No S materialization; out kernel deleted.
// Dynamic smem 66KB: [As|Bs] (mainloop) overlaid by [Ps], then [xs].
// Grid (8 j, 4 i, 4 b) = 128 blocks.
// ---------------------------------------------------------------------------
#define SM_BS   20480                    // Bs offset
#define SM_XS   34816                    // xs offset (after Ps 128*68*4)
#define SM_TOT  (SM_XS + 64 * Dx * 4)    // 67584

__global__ __launch_bounds__(256) void gemm_av_kernel(const float* __restrict__ x) {
    extern __shared__ char dynsm[];
    __half (*As)[128][40] = reinterpret_cast<__half(*)[128][40]>(dynsm);
    __half (*Bs)[64][40]  = reinterpret_cast<__half(*)[64][40]>(dynsm + SM_BS);
    float (*Ps)[68]       = reinterpret_cast<float(*)[68]>(dynsm);       // overlays As/Bs
    float (*xs)[Dx]       = reinterpret_cast<float(*)[Dx]>(dynsm + SM_XS);
    __shared__ float rs[2][128];

    int jb = blockIdx.x;            // j tile 0..7
    int b = blockIdx.z;
    int i0 = blockIdx.y * 128;
    int j0 = jb * 64;
    const __half* FQ = (const __half*)g_FQ4 + ((size_t)b * Lx + i0) * KP;
    const __half* FK = (const __half*)g_FK4 + ((size_t)b * Lx + j0) * KP;

    int tid = threadIdx.x;
    int warp = tid >> 5, lane = tid & 31;
    int wr = warp >> 1, wc = warp & 1;

    float acc[2][4][4];
#pragma unroll
    for (int mt = 0; mt < 2; mt++)
#pragma unroll
        for (int nt = 0; nt < 4; nt++)
#pragma unroll
            for (int q = 0; q < 4; q++) acc[mt][nt][q] = 0.f;

    const int NCH = KP / 32;   // 96 chunks (full K)

    {
#pragma unroll
        for (int l = 0; l < 2; l++) {
            int idx = tid + 256 * l;
            int row = idx >> 2, seg = idx & 3;
            cp16(saddr(&As[0][row][seg * 8]), FQ + (size_t)row * KP + seg * 8);
        }
        {
            int row = tid >> 2, seg = tid & 3;
            cp16(saddr(&Bs[0][row][seg * 8]), FK + (size_t)row * KP + seg * 8);
        }
        asm volatile("cp.async.commit_group;");
    }

    int buf = 0;
    for (int c = 0; c < NCH; c++) {
        if (c + 1 < NCH) {
            int co = (c + 1) * 32;
#pragma unroll
            for (int l = 0; l < 2; l++) {
                int idx = tid + 256 * l;
                int row = idx >> 2, seg = idx & 3;
                cp16(saddr(&As[buf ^ 1][row][seg * 8]),
                     FQ + (size_t)row * KP + co + seg * 8);
            }
            {
                int row = tid >> 2, seg = tid & 3;
                cp16(saddr(&Bs[buf ^ 1][row][seg * 8]),
                     FK + (size_t)row * KP + co + seg * 8);
            }
            asm volatile("cp.async.commit_group;");
            asm volatile("cp.async.wait_group 1;");
        } else {
            asm volatile("cp.async.wait_group 0;");
        }
        __syncthreads();

#pragma unroll
        for (int ks = 0; ks < 2; ks++) {
            unsigned a[2][4], bb[2][4];
#pragma unroll
            for (int mt = 0; mt < 2; mt++) {
                int row = 32 * wr + 16 * mt + (lane & 7) + 8 * ((lane >> 3) & 1);
                int col = ks * 16 + 8 * (lane >> 4);
                ldsm_x4(a[mt][0], a[mt][1], a[mt][2], a[mt][3],
                        saddr(&As[buf][row][col]));
            }
#pragma unroll
            for (int p = 0; p < 2; p++) {
                int n = 32 * wc + 16 * p + (lane & 7) + 8 * (lane >> 4);
                int col = ks * 16 + 8 * ((lane >> 3) & 1);
                ldsm_x4(bb[p][0], bb[p][1], bb[p][2], bb[p][3],
                        saddr(&Bs[buf][n][col]));
            }
#pragma unroll
            for (int mt = 0; mt < 2; mt++)
#pragma unroll
                for (int nt = 0; nt < 4; nt++)
                    mma16816(acc[mt][nt], a[mt],
                             bb[nt >> 1][2 * (nt & 1)], bb[nt >> 1][2 * (nt & 1) + 1]);
        }
        __syncthreads();
        buf ^= 1;
    }
    // all warps past final sync: As/Bs dead, safe to overlay with Ps.

    // exp2 + P->smem + per-fragment row sums
    int g = lane >> 2, tg = lane & 3;
    float rsum[4] = {0.f, 0.f, 0.f, 0.f};  // rows 32wr+16mt+g (+8)
#pragma unroll
    for (int mt = 0; mt < 2; mt++)
#pragma unroll
        for (int nt = 0; nt < 4; nt++) {
            int r = 32 * wr + 16 * mt + g;
            int cc = 32 * wc + 8 * nt + 2 * tg;
            float p0 = ex2_fast(acc[mt][nt][0]);
            float p1 = ex2_fast(acc[mt][nt][1]);
            float p2 = ex2_fast(acc[mt][nt][2]);
            float p3 = ex2_fast(acc[mt][nt][3]);
            rsum[2 * mt + 0] += p0 + p1;
            rsum[2 * mt + 1] += p2 + p3;
            *(float2*)&Ps[r][cc]     = make_float2(p0, p1);
            *(float2*)&Ps[r + 8][cc] = make_float2(p2, p3);
        }
    // reduce rsum over tg (lanes differing in bits 0,1 share the same row g)
#pragma unroll
    for (int rr = 0; rr < 4; rr++) {
        rsum[rr] += __shfl_xor_sync(0xffffffffu, rsum[rr], 1);
        rsum[rr] += __shfl_xor_sync(0xffffffffu, rsum[rr], 2);
    }
    if (tg == 0) {
#pragma unroll
        for (int mt = 0; mt < 2; mt++) {
            rs[wc][32 * wr + 16 * mt + g]     = rsum[2 * mt + 0];
            rs[wc][32 * wr + 16 * mt + g + 8] = rsum[2 * mt + 1];
        }
    }

    // stage x tile [64 j][128 d] (L2-hot; 8 float4 per thread, coalesced)
    {
        const float4* xb4 = (const float4*)(x + ((size_t)b * Lx + j0) * Dx);
#pragma unroll
        for (int t = 0; t < 8; t++) {
            int idx = tid + 256 * t;
            int row = idx >> 5, c4 = idx & 31;
            *(float4*)&xs[row][4 * c4] = xb4[idx];
        }
    }
    __syncthreads();

    // partial row sums out
    if (tid < 128)
        g_ps[jb][(size_t)b * Lx + i0 + tid] = rs[0][tid] + rs[1][tid];

    // f32 AV: thread owns column d for 64 rows (16 tiles x 4 rows)
    int d = tid & 127;
    int ig = tid >> 7;
    float* ga = g_acc[jb] + ((size_t)b * Lx + i0) * Dx + d;
#pragma unroll 1
    for (int rt = 0; rt < 16; rt++) {
        int rbase = rt * 8 + ig * 4;
        float a0 = 0.f, a1 = 0.f, a2 = 0.f, a3 = 0.f;
#pragma unroll
        for (int j4 = 0; j4 < 16; j4++) {
            float xv0 = xs[4 * j4 + 0][d];
            float xv1 = xs[4 * j4 + 1][d];
            float xv2 = xs[4 * j4 + 2][d];
            float xv3 = xs[4 * j4 + 3][d];
            float4 p0 = *(const float4*)&Ps[rbase + 0][4 * j4];
            float4 p1 = *(const float4*)&Ps[rbase + 1][4 * j4];
            float4 p2 = *(const float4*)&Ps[rbase + 2][4 * j4];
            float4 p3 = *(const float4*)&Ps[rbase + 3][4 * j4];
            a0 = fmaf(p0.x, xv0, fmaf(p0.y, xv1, fmaf(p0.z, xv2, fmaf(p0.w, xv3, a0))));
            a1 = fmaf(p1.x, xv0, fmaf(p1.y, xv1, fmaf(p1.z, xv2, fmaf(p1.w, xv3, a1))));
            a2 = fmaf(p2.x, xv0, fmaf(p2.y, xv1, fmaf(p2.z, xv2, fmaf(p2.w, xv3, a2))));
            a3 = fmaf(p3.x, xv0, fmaf(p3.y, xv1, fmaf(p3.z, xv2, fmaf(p3.w, xv3, a3))));
        }
        ga[(size_t)(rbase + 0) * Dx] = a0;
        ga[(size_t)(rbase + 1) * Dx] = a1;
        ga[(size_t)(rbase + 2) * Dx] = a2;
        ga[(size_t)(rbase + 3) * Dx] = a3;
    }
}

// ---------------------------------------------------------------------------
// Kernel 4: combine j-split partials: out = (sum_jb acc) / (sum_jb ps).
// 8 rows per block; all reads L2-hot (8MB partials).
// ---------------------------------------------------------------------------
__global__ __launch_bounds__(256) void combine_kernel(float* __restrict__ out) {
    __shared__ float inv[8];
    int row0 = blockIdx.x * 8;

    if (threadIdx.x < 8) {
        int row = row0 + threadIdx.x;
        float s = 0.f;
#pragma unroll
        for (int jb = 0; jb < NJ; jb++) s += g_ps[jb][row];
        inv[threadIdx.x] = 1.0f / s;
    }
    __syncthreads();

#pragma unroll
    for (int k = 0; k < 4; k++) {
        int idx = threadIdx.x + 256 * k;      // 0..1023
        int r = idx >> 7, d = idx & 127;
        size_t off = (size_t)(row0 + r) * Dx + d;
        float v = 0.f;
#pragma unroll
        for (int jb = 0; jb < NJ; jb++) v += g_acc[jb][off];
        out[off] = v * inv[r];
    }
}

// ---------------------------------------------------------------------------
extern "C" void kernel_launch(void* const* d_in, const int* in_sizes, int n_in,
                              void* d_out, int out_size) {
    const float* x  = (const float*)d_in[0];
    // d_in[1] = mask (bool) — intentionally unused: reference's masked_fill is
    // out-of-place and discarded, so mask has no effect on the output.
    const float* Wq = (const float*)d_in[2];
    const float* bq = (const float*)d_in[3];
    const float* Wk = (const float*)d_in[4];
    const float* bk = (const float*)d_in[5];
    const float* w  = (const float*)d_in[6];
    // d_in[7] = bw — unused: constant score shift cancels in softmax.
    float* out = (float*)d_out;

    // idempotent, host-side, capture-legal; no allocation involved
    cudaFuncSetAttribute(gemm_av_kernel,
                         cudaFuncAttributeMaxDynamicSharedMemorySize, SM_TOT);

    dim3 g1(Bx * Lx / 16, 2);
    qk_kernel<<<g1, 256>>>(x, Wq, bq, Wk, bk);

    dim3 gf(Bx * Lx / 4, 2);
    feat_kernel<<<gf, 128>>>(w);

    dim3 gg(NJ, Lx / 128, Bx);
    gemm_av_kernel<<<gg, 256, SM_TOT>>>(x);

    combine_kernel<<<Bx * Lx / 8, 256>>>(out);
}

// round 16
// speedup vs baseline: 1.0909x; 1.0909x over previous
#include <cuda_runtime.h>
#include <cuda_fp16.h>

#define Bx 4
#define Lx 512
#define Dx 128
#define NH 12              // harmonics m = 1,3,...,23
#define KP (NH * 2 * Dx)   // 3072 feature dim
#define NJ 8               // j-tiles (=partials)
#define LOG2E 1.4426950408889634f
#define OMEGA1 0.22439948f // pi/14

// Scratch (static device arrays: allowed; no allocations anywhere)
__device__ float g_Q[Bx * Lx * Dx];
__device__ float g_K[Bx * Lx * Dx];
__device__ uint4 g_FQ4[(size_t)Bx * Lx * KP / 8];
__device__ uint4 g_FK4[(size_t)Bx * Lx * KP / 8];
__device__ float g_acc[NJ][(size_t)Bx * Lx * Dx]; // j-split AV partials
__device__ float g_ps[NJ][Bx * Lx];               // j-split row-sum partials

// Fourier sine coefficients of mirrored tanh: b_m = pi / (7 sinh(m pi^2/28))
__device__ __constant__ float c_B[NH] = {
    1.24737f,     0.354585f,   0.158755f,   0.0766902f,
    0.0376905f,   0.0186002f,  0.00918841f, 0.00454012f,
    0.00224348f,  0.00110862f, 0.000547829f, 0.000270714f
};

__device__ __forceinline__ unsigned saddr(const void* p) {
    return (unsigned)__cvta_generic_to_shared(p);
}
__device__ __forceinline__ void cp16(unsigned dst, const void* src) {
    asm volatile("cp.async.cg.shared.global [%0], [%1], 16;" :: "r"(dst), "l"(src));
}
__device__ __forceinline__ void ldsm_x4(unsigned& r0, unsigned& r1, unsigned& r2,
                                        unsigned& r3, unsigned addr) {
    asm volatile("ldmatrix.sync.aligned.m8n8.x4.shared.b16 {%0,%1,%2,%3}, [%4];"
                 : "=r"(r0), "=r"(r1), "=r"(r2), "=r"(r3) : "r"(addr));
}
__device__ __forceinline__ void ldsm_x4_t(unsigned& r0, unsigned& r1, unsigned& r2,
                                          unsigned& r3, unsigned addr) {
    asm volatile("ldmatrix.sync.aligned.m8n8.x4.trans.shared.b16 {%0,%1,%2,%3}, [%4];"
                 : "=r"(r0), "=r"(r1), "=r"(r2), "=r"(r3) : "r"(addr));
}
__device__ __forceinline__ void mma16816(float* c, const unsigned* a,
                                         unsigned b0, unsigned b1) {
    asm volatile(
        "mma.sync.aligned.m16n8k16.row.col.f32.f16.f16.f32 "
        "{%0,%1,%2,%3}, {%4,%5,%6,%7}, {%8,%9}, {%0,%1,%2,%3};"
        : "+f"(c[0]), "+f"(c[1]), "+f"(c[2]), "+f"(c[3])
        : "r"(a[0]), "r"(a[1]), "r"(a[2]), "r"(a[3]), "r"(b0), "r"(b1));
}
__device__ __forceinline__ float ex2_fast(float v) {
    float y;
    asm("ex2.approx.f32 %0, %1;" : "=f"(y) : "f"(v));
    return y;
}

// ---------------------------------------------------------------------------
// Kernel 1: projections q = x Wq^T + bq, k = x Wk^T + bk.
// ---------------------------------------------------------------------------
__global__ __launch_bounds__(256) void qk_kernel(
        const float* __restrict__ x,
        const float* __restrict__ Wq, const float* __restrict__ bq,
        const float* __restrict__ Wk, const float* __restrict__ bk) {
    __shared__ float Wsh[32][130];
    __shared__ float xsh[32][20];

    int which = blockIdx.y;
    int row0 = blockIdx.x * 16;
    const float* W = which ? Wk : Wq;
    const float* bias = which ? bk : bq;
    float* outp = which ? g_K : g_Q;

    int tid = threadIdx.x;
    int e0 = 2 * (tid & 63);
    int rg = tid >> 6;

    const float4* W4 = (const float4*)W;
    const float4* x4 = (const float4*)(x + (size_t)row0 * Dx);

    float4 wreg[4];
    float4 xreg;
#pragma unroll
    for (int k = 0; k < 4; k++) {
        int idx = tid + 256 * k;
        wreg[k] = W4[(size_t)(idx >> 3) * 32 + (idx & 7)];
    }
    if (tid < 128) xreg = x4[(size_t)(tid >> 3) * 32 + (tid & 7)];

    float acc[4][2];
#pragma unroll
    for (int r = 0; r < 4; r++) { acc[r][0] = 0.f; acc[r][1] = 0.f; }

    for (int c = 0; c < 4; c++) {
        __syncthreads();
#pragma unroll
        for (int k = 0; k < 4; k++) {
            int idx = tid + 256 * k;
            int e = idx >> 3, j4 = idx & 7;
            Wsh[4 * j4 + 0][e] = wreg[k].x;
            Wsh[4 * j4 + 1][e] = wreg[k].y;
            Wsh[4 * j4 + 2][e] = wreg[k].z;
            Wsh[4 * j4 + 3][e] = wreg[k].w;
        }
        if (tid < 128) {
            int r = tid >> 3, j4 = tid & 7;
            xsh[4 * j4 + 0][r] = xreg.x;
            xsh[4 * j4 + 1][r] = xreg.y;
            xsh[4 * j4 + 2][r] = xreg.z;
            xsh[4 * j4 + 3][r] = xreg.w;
        }
        __syncthreads();

        if (c < 3) {
            int dc4n = (c + 1) * 8;
#pragma unroll
            for (int k = 0; k < 4; k++) {
                int idx = tid + 256 * k;
                wreg[k] = W4[(size_t)(idx >> 3) * 32 + dc4n + (idx & 7)];
            }
            if (tid < 128) xreg = x4[(size_t)(tid >> 3) * 32 + dc4n + (tid & 7)];
        }

#pragma unroll
        for (int d = 0; d < 32; d++) {
            float2 wv = *(const float2*)&Wsh[d][e0];
            float4 xv = *(const float4*)&xsh[d][4 * rg];
            acc[0][0] += wv.x * xv.x;  acc[0][1] += wv.y * xv.x;
            acc[1][0] += wv.x * xv.y;  acc[1][1] += wv.y * xv.y;
            acc[2][0] += wv.x * xv.z;  acc[2][1] += wv.y * xv.z;
            acc[3][0] += wv.x * xv.w;  acc[3][1] += wv.y * xv.w;
        }
    }

    float b0 = bias[e0], b1 = bias[e0 + 1];
#pragma unroll
    for (int r = 0; r < 4; r++) {
        int row = row0 + 4 * rg + r;
        *(float2*)&outp[(size_t)row * Dx + e0] =
            make_float2(acc[r][0] + b0, acc[r][1] + b1);
    }
}

// ---------------------------------------------------------------------------
// Kernel 2: Fourier features (unchanged).
// ---------------------------------------------------------------------------
__global__ __launch_bounds__(128) void feat_kernel(const float* __restrict__ w) {
    __shared__ unsigned sbuf[4][NH * Dx];

    int which = blockIdx.y;
    int row0 = blockIdx.x * 4;
    const float* P = which ? g_K : g_Q;
    uint4* F4 = which ? g_FK4 : g_FQ4;

    int d = threadIdx.x;
    float wp = w[d] * LOG2E;

#pragma unroll
    for (int r = 0; r < 4; r++) {
        float z = P[(size_t)(row0 + r) * Dx + d];
        float s1, c1;
        __sincosf(OMEGA1 * z, &s1, &c1);
        float s2 = 2.f * s1 * c1;
        float c2 = fmaf(-2.f * s1, s1, 1.f);
        float sm = s1, cm = c1;
#pragma unroll
        for (int h = 0; h < NH; h++) {
            __half2 hv;
            if (which == 0) {
                float sc = c_B[h] * wp;
                hv = __float22half2_rn(make_float2(sc * sm, sc * cm));
            } else {
                hv = __float22half2_rn(make_float2(cm, sm));
            }
            sbuf[r][h * Dx + d] = *(unsigned*)&hv;
            float ns = fmaf(sm, c2, cm * s2);
            float nc = fmaf(cm, c2, -sm * s2);
            sm = ns; cm = nc;
        }
    }
    __syncthreads();

    const uint4* sb4 = (const uint4*)sbuf;
    for (int i = threadIdx.x; i < 4 * (KP / 8); i += 128) {
        int r = i / (KP / 8), off = i % (KP / 8);
        F4[(size_t)(row0 + r) * (KP / 8) + off] = sb4[i];
    }
}

// ---------------------------------------------------------------------------
// Kernel 3 (fused, all-HMMA): i64 x j64 tile, full K=3072.
//  S = FQ@FK^T (HMMA f32 acc) -> p = exp2(S) regs -> rowsums f32 -> P f16 smem
//  -> AV: O = P @ x_f16 via HMMA (m64 n128 k64) -> g_acc partial.
// smem 26.6KB; grid (8 j, 8 i, 4 b) = 256 blocks; 8 warps = 2(m) x 4(n).
// ---------------------------------------------------------------------------
#define SM_BSOFF 10240                    // Bs after As (2*64*40*2)
#define SM_XSOFF 9216                     // xs after Ps (64*72*2)
#define SM_TOT   (SM_XSOFF + 64 * 136 * 2)  // 26624

__global__ __launch_bounds__(256) void gemm_av_kernel(const float* __restrict__ x) {
    extern __shared__ char dynsm[];
    __half (*As)[64][40] = reinterpret_cast<__half(*)[64][40]>(dynsm);
    __half (*Bs)[64][40] = reinterpret_cast<__half(*)[64][40]>(dynsm + SM_BSOFF);
    __half (*Ps)[72]     = reinterpret_cast<__half(*)[72]>(dynsm);        // overlay
    __half (*xs)[136]    = reinterpret_cast<__half(*)[136]>(dynsm + SM_XSOFF);
    __shared__ float rs[4][64];

    int jb = blockIdx.x;
    int b = blockIdx.z;
    int i0 = blockIdx.y * 64;
    int j0 = jb * 64;
    const __half* FQ = (const __half*)g_FQ4 + ((size_t)b * Lx + i0) * KP;
    const __half* FK = (const __half*)g_FK4 + ((size_t)b * Lx + j0) * KP;

    int tid = threadIdx.x;
    int warp = tid >> 5, lane = tid & 31;
    int wr = warp >> 2, wc = warp & 3;      // 2 x 4

    float acc[2][2][4];
#pragma unroll
    for (int mt = 0; mt < 2; mt++)
#pragma unroll
        for (int nt = 0; nt < 2; nt++)
#pragma unroll
            for (int q = 0; q < 4; q++) acc[mt][nt][q] = 0.f;

    const int NCH = KP / 32;   // 96 chunks

    {   // prologue stage 0: A chunk 64x32 (4KB), B chunk 64x32 (4KB)
        int row = tid >> 2, seg = tid & 3;
        cp16(saddr(&As[0][row][seg * 8]), FQ + (size_t)row * KP + seg * 8);
        cp16(saddr(&Bs[0][row][seg * 8]), FK + (size_t)row * KP + seg * 8);
        asm volatile("cp.async.commit_group;");
    }

    int buf = 0;
    for (int c = 0; c < NCH; c++) {
        if (c + 1 < NCH) {
            int co = (c + 1) * 32;
            int row = tid >> 2, seg = tid & 3;
            cp16(saddr(&As[buf ^ 1][row][seg * 8]),
                 FQ + (size_t)row * KP + co + seg * 8);
            cp16(saddr(&Bs[buf ^ 1][row][seg * 8]),
                 FK + (size_t)row * KP + co + seg * 8);
            asm volatile("cp.async.commit_group;");
            asm volatile("cp.async.wait_group 1;");
        } else {
            asm volatile("cp.async.wait_group 0;");
        }
        __syncthreads();

#pragma unroll
        for (int ks = 0; ks < 2; ks++) {
            unsigned a[2][4], bb[4];
#pragma unroll
            for (int mt = 0; mt < 2; mt++) {
                int row = 32 * wr + 16 * mt + (lane & 7) + 8 * ((lane >> 3) & 1);
                int col = ks * 16 + 8 * (lane >> 4);
                ldsm_x4(a[mt][0], a[mt][1], a[mt][2], a[mt][3],
                        saddr(&As[buf][row][col]));
            }
            {
                int n = 16 * wc + (lane & 7) + 8 * (lane >> 4);
                int col = ks * 16 + 8 * ((lane >> 3) & 1);
                ldsm_x4(bb[0], bb[1], bb[2], bb[3], saddr(&Bs[buf][n][col]));
            }
#pragma unroll
            for (int mt = 0; mt < 2; mt++)
#pragma unroll
                for (int nt = 0; nt < 2; nt++)
                    mma16816(acc[mt][nt], a[mt], bb[2 * nt], bb[2 * nt + 1]);
        }
        __syncthreads();
        buf ^= 1;
    }
    // mainloop done; As/Bs dead.

    // exp2 + f32 rowsums + P -> f16 smem
    int g = lane >> 2, tg = lane & 3;
    float rsum[4] = {0.f, 0.f, 0.f, 0.f};   // rows 32wr+16mt+{g,g+8}
#pragma unroll
    for (int mt = 0; mt < 2; mt++)
#pragma unroll
        for (int nt = 0; nt < 2; nt++) {
            int r = 32 * wr + 16 * mt + g;
            int n = 16 * wc + 8 * nt + 2 * tg;
            float p0 = ex2_fast(acc[mt][nt][0]);
            float p1 = ex2_fast(acc[mt][nt][1]);
            float p2 = ex2_fast(acc[mt][nt][2]);
            float p3 = ex2_fast(acc[mt][nt][3]);
            rsum[2 * mt + 0] += p0 + p1;
            rsum[2 * mt + 1] += p2 + p3;
            *(__half2*)&Ps[r][n]     = __float22half2_rn(make_float2(p0, p1));
            *(__half2*)&Ps[r + 8][n] = __float22half2_rn(make_float2(p2, p3));
        }
#pragma unroll
    for (int rr = 0; rr < 4; rr++) {
        rsum[rr] += __shfl_xor_sync(0xffffffffu, rsum[rr], 1);
        rsum[rr] += __shfl_xor_sync(0xffffffffu, rsum[rr], 2);
    }
    if (tg == 0) {
#pragma unroll
        for (int mt = 0; mt < 2; mt++) {
            rs[wc][32 * wr + 16 * mt + g]     = rsum[2 * mt + 0];
            rs[wc][32 * wr + 16 * mt + g + 8] = rsum[2 * mt + 1];
        }
    }

    // stage x tile [64 j][128 d] as f16 (L2-hot, 8 float4/thread coalesced)
    {
        const float4* xb4 = (const float4*)(x + ((size_t)b * Lx + j0) * Dx);
#pragma unroll
        for (int t = 0; t < 8; t++) {
            int idx = tid + 256 * t;
            int row = idx >> 5, c4 = idx & 31;
            float4 v = xb4[idx];
            *(__half2*)&xs[row][4 * c4]     = __float22half2_rn(make_float2(v.x, v.y));
            *(__half2*)&xs[row][4 * c4 + 2] = __float22half2_rn(make_float2(v.z, v.w));
        }
    }
    __syncthreads();

    if (tid < 64)
        g_ps[jb][(size_t)b * Lx + i0 + tid] =
            rs[0][tid] + rs[1][tid] + rs[2][tid] + rs[3][tid];

    // AV HMMA: O[64 x 128] = P[64 x 64] @ X[64 x 128]; warp tile m32 x n32
    float acc2[2][4][4];
#pragma unroll
    for (int mt = 0; mt < 2; mt++)
#pragma unroll
        for (int nt = 0; nt < 4; nt++)
#pragma unroll
            for (int q = 0; q < 4; q++) acc2[mt][nt][q] = 0.f;

#pragma unroll
    for (int ks = 0; ks < 4; ks++) {
        unsigned a[2][4], bb2[2][4];
#pragma unroll
        for (int mt = 0; mt < 2; mt++) {
            int row = 32 * wr + 16 * mt + (lane & 7) + 8 * ((lane >> 3) & 1);
            int col = ks * 16 + 8 * (lane >> 4);
            ldsm_x4(a[mt][0], a[mt][1], a[mt][2], a[mt][3],
                    saddr(&Ps[row][col]));
        }
#pragma unroll
        for (int nt2 = 0; nt2 < 2; nt2++) {
            int krow = 16 * ks + (lane & 15);
            int ncol = 32 * wc + 16 * nt2 + 8 * (lane >> 4);
            ldsm_x4_t(bb2[nt2][0], bb2[nt2][1], bb2[nt2][2], bb2[nt2][3],
                      saddr(&xs[krow][ncol]));
        }
#pragma unroll
        for (int mt = 0; mt < 2; mt++)
#pragma unroll
            for (int nt = 0; nt < 4; nt++)
                mma16816(acc2[mt][nt], a[mt],
                         bb2[nt >> 1][2 * (nt & 1)], bb2[nt >> 1][2 * (nt & 1) + 1]);
    }

    // write O partial fragments
    float* ga = g_acc[jb] + ((size_t)b * Lx + i0) * Dx;
#pragma unroll
    for (int mt = 0; mt < 2; mt++)
#pragma unroll
        for (int nt = 0; nt < 4; nt++) {
            int r = 32 * wr + 16 * mt + g;
            int dn = 32 * wc + 8 * nt + 2 * tg;
            *(float2*)&ga[(size_t)r * Dx + dn] =
                make_float2(acc2[mt][nt][0], acc2[mt][nt][1]);
            *(float2*)&ga[(size_t)(r + 8) * Dx + dn] =
                make_float2(acc2[mt][nt][2], acc2[mt][nt][3]);
        }
}

// ---------------------------------------------------------------------------
// Kernel 4: combine: out[idx] = sum_jb acc / sum_jb ps. One thread per
// element, 16 independent L2-hot loads (MLP 16), grid 1024.
// ---------------------------------------------------------------------------
__global__ __launch_bounds__(256) void combine_kernel(float* __restrict__ out) {
    int idx = blockIdx.x * 256 + threadIdx.x;   // 0 .. B*L*D-1
    int r = idx >> 7;
    float s = 0.f, v = 0.f;
#pragma unroll
    for (int jb = 0; jb < NJ; jb++) {
        s += g_ps[jb][r];
        v += g_acc[jb][idx];
    }
    out[idx] = v * (1.0f / s);
}

// ---------------------------------------------------------------------------
extern "C" void kernel_launch(void* const* d_in, const int* in_sizes, int n_in,
                              void* d_out, int out_size) {
    const float* x  = (const float*)d_in[0];
    // d_in[1] = mask (bool) — intentionally unused: reference's masked_fill is
    // out-of-place and discarded, so mask has no effect on the output.
    const float* Wq = (const float*)d_in[2];
    const float* bq = (const float*)d_in[3];
    const float* Wk = (const float*)d_in[4];
    const float* bk = (const float*)d_in[5];
    const float* w  = (const float*)d_in[6];
    // d_in[7] = bw — unused: constant score shift cancels in softmax.
    float* out = (float*)d_out;

    dim3 g1(Bx * Lx / 16, 2);
    qk_kernel<<<g1, 256>>>(x, Wq, bq, Wk, bk);

    dim3 gf(Bx * Lx / 4, 2);
    feat_kernel<<<gf, 128>>>(w);

    dim3 gg(NJ, Lx / 64, Bx);
    gemm_av_kernel<<<gg, 256, SM_TOT>>>(x);

    combine_kernel<<<Bx * Lx * Dx / 256, 256>>>(out);
}

// round 17
// speedup vs baseline: 1.2857x; 1.1786x over previous
#include <cuda_runtime.h>
#include <cuda_fp16.h>

#define Bx 4
#define Lx 512
#define Dx 128
#define NH 12              // harmonics m = 1,3,...,23
#define KP (NH * 2 * Dx)   // 3072 feature dim (half elements); KP/2 words/row
#define NJ 8               // j-tiles (=partials)
#define LOG2E 1.4426950408889634f
#define OMEGA1 0.22439948f // pi/14

// Scratch (static device arrays: allowed; no allocations anywhere)
__device__ uint4 g_FQ4[(size_t)Bx * Lx * KP / 8];
__device__ uint4 g_FK4[(size_t)Bx * Lx * KP / 8];
__device__ float g_acc[NJ][(size_t)Bx * Lx * Dx]; // j-split AV partials
__device__ float g_ps[NJ][Bx * Lx];               // j-split row-sum partials

// Fourier sine coefficients of mirrored tanh: b_m = pi / (7 sinh(m pi^2/28))
__device__ __constant__ float c_B[NH] = {
    1.24737f,     0.354585f,   0.158755f,   0.0766902f,
    0.0376905f,   0.0186002f,  0.00918841f, 0.00454012f,
    0.00224348f,  0.00110862f, 0.000547829f, 0.000270714f
};

__device__ __forceinline__ unsigned saddr(const void* p) {
    return (unsigned)__cvta_generic_to_shared(p);
}
__device__ __forceinline__ void cp16(unsigned dst, const void* src) {
    asm volatile("cp.async.cg.shared.global [%0], [%1], 16;" :: "r"(dst), "l"(src));
}
__device__ __forceinline__ void ldsm_x4(unsigned& r0, unsigned& r1, unsigned& r2,
                                        unsigned& r3, unsigned addr) {
    asm volatile("ldmatrix.sync.aligned.m8n8.x4.shared.b16 {%0,%1,%2,%3}, [%4];"
                 : "=r"(r0), "=r"(r1), "=r"(r2), "=r"(r3) : "r"(addr));
}
__device__ __forceinline__ void ldsm_x4_t(unsigned& r0, unsigned& r1, unsigned& r2,
                                          unsigned& r3, unsigned addr) {
    asm volatile("ldmatrix.sync.aligned.m8n8.x4.trans.shared.b16 {%0,%1,%2,%3}, [%4];"
                 : "=r"(r0), "=r"(r1), "=r"(r2), "=r"(r3) : "r"(addr));
}
__device__ __forceinline__ void mma16816(float* c, const unsigned* a,
                                         unsigned b0, unsigned b1) {
    asm volatile(
        "mma.sync.aligned.m16n8k16.row.col.f32.f16.f16.f32 "
        "{%0,%1,%2,%3}, {%4,%5,%6,%7}, {%8,%9}, {%0,%1,%2,%3};"
        : "+f"(c[0]), "+f"(c[1]), "+f"(c[2]), "+f"(c[3])
        : "r"(a[0]), "r"(a[1]), "r"(a[2]), "r"(a[3]), "r"(b0), "r"(b1));
}
__device__ __forceinline__ float ex2_fast(float v) {
    float y;
    asm("ex2.approx.f32 %0, %1;" : "=f"(y) : "f"(v));
    return y;
}

// ---------------------------------------------------------------------------
// Kernel 1 (fused): proj = x W^T + b, epilogue computes Fourier features
// directly from the register-resident projections (no g_Q/g_K round trip).
// Q side word [row][h*128+d]: (b_h w'_d sin(w_h q), b_h w'_d cos(w_h q))
// K side word:               (cos(w_h k), sin(w_h k))
// ---------------------------------------------------------------------------
__global__ __launch_bounds__(256) void qkfeat_kernel(
        const float* __restrict__ x,
        const float* __restrict__ Wq, const float* __restrict__ bq,
        const float* __restrict__ Wk, const float* __restrict__ bk,
        const float* __restrict__ w) {
    __shared__ float Wsh[32][130];
    __shared__ float xsh[32][20];

    int which = blockIdx.y;
    int row0 = blockIdx.x * 16;
    const float* W = which ? Wk : Wq;
    const float* bias = which ? bk : bq;
    unsigned* Fout = (unsigned*)(which ? g_FK4 : g_FQ4);

    int tid = threadIdx.x;
    int eidx = tid & 63;
    int e0 = 2 * eidx;
    int rg = tid >> 6;

    const float4* W4 = (const float4*)W;
    const float4* x4 = (const float4*)(x + (size_t)row0 * Dx);

    float4 wreg[4];
    float4 xreg;
#pragma unroll
    for (int k = 0; k < 4; k++) {
        int idx = tid + 256 * k;
        wreg[k] = W4[(size_t)(idx >> 3) * 32 + (idx & 7)];
    }
    if (tid < 128) xreg = x4[(size_t)(tid >> 3) * 32 + (tid & 7)];

    float acc[4][2];
#pragma unroll
    for (int r = 0; r < 4; r++) { acc[r][0] = 0.f; acc[r][1] = 0.f; }

    for (int c = 0; c < 4; c++) {
        __syncthreads();
#pragma unroll
        for (int k = 0; k < 4; k++) {
            int idx = tid + 256 * k;
            int e = idx >> 3, j4 = idx & 7;
            Wsh[4 * j4 + 0][e] = wreg[k].x;
            Wsh[4 * j4 + 1][e] = wreg[k].y;
            Wsh[4 * j4 + 2][e] = wreg[k].z;
            Wsh[4 * j4 + 3][e] = wreg[k].w;
        }
        if (tid < 128) {
            int r = tid >> 3, j4 = tid & 7;
            xsh[4 * j4 + 0][r] = xreg.x;
            xsh[4 * j4 + 1][r] = xreg.y;
            xsh[4 * j4 + 2][r] = xreg.z;
            xsh[4 * j4 + 3][r] = xreg.w;
        }
        __syncthreads();

        if (c < 3) {
            int dc4n = (c + 1) * 8;
#pragma unroll
            for (int k = 0; k < 4; k++) {
                int idx = tid + 256 * k;
                wreg[k] = W4[(size_t)(idx >> 3) * 32 + dc4n + (idx & 7)];
            }
            if (tid < 128) xreg = x4[(size_t)(tid >> 3) * 32 + dc4n + (tid & 7)];
        }

#pragma unroll
        for (int d = 0; d < 32; d++) {
            float2 wv = *(const float2*)&Wsh[d][e0];
            float4 xv = *(const float4*)&xsh[d][4 * rg];
            acc[0][0] += wv.x * xv.x;  acc[0][1] += wv.y * xv.x;
            acc[1][0] += wv.x * xv.y;  acc[1][1] += wv.y * xv.y;
            acc[2][0] += wv.x * xv.z;  acc[2][1] += wv.y * xv.z;
            acc[3][0] += wv.x * xv.w;  acc[3][1] += wv.y * xv.w;
        }
    }

    float b0 = bias[e0], b1 = bias[e0 + 1];
    float wl0 = w[e0] * LOG2E, wl1 = w[e0 + 1] * LOG2E;

#pragma unroll
    for (int r = 0; r < 4; r++) {
        int row = row0 + 4 * rg + r;
        float z0 = acc[r][0] + b0;
        float z1 = acc[r][1] + b1;
        float s1a, c1a, s1b, c1b;
        __sincosf(OMEGA1 * z0, &s1a, &c1a);
        __sincosf(OMEGA1 * z1, &s1b, &c1b);
        float s2a = 2.f * s1a * c1a, c2a = fmaf(-2.f * s1a, s1a, 1.f);
        float s2b = 2.f * s1b * c1b, c2b = fmaf(-2.f * s1b, s1b, 1.f);
        float sma = s1a, cma = c1a, smb = s1b, cmb = c1b;

        uint2* dst = (uint2*)(Fout + (size_t)row * (KP / 2));
#pragma unroll
        for (int h = 0; h < NH; h++) {
            __half2 hv0, hv1;
            if (which == 0) {
                float sc0 = c_B[h] * wl0, sc1 = c_B[h] * wl1;
                hv0 = __float22half2_rn(make_float2(sc0 * sma, sc0 * cma));
                hv1 = __float22half2_rn(make_float2(sc1 * smb, sc1 * cmb));
            } else {
                hv0 = __float22half2_rn(make_float2(cma, sma));
                hv1 = __float22half2_rn(make_float2(cmb, smb));
            }
            uint2 u;
            u.x = *(unsigned*)&hv0;
            u.y = *(unsigned*)&hv1;
            dst[h * 64 + eidx] = u;   // word h*128+e0, coalesced over eidx

            float ns = fmaf(sma, c2a, cma * s2a);
            cma = fmaf(cma, c2a, -sma * s2a);
            sma = ns;
            ns = fmaf(smb, c2b, cmb * s2b);
            cmb = fmaf(cmb, c2b, -smb * s2b);
            smb = ns;
        }
    }
}

// ---------------------------------------------------------------------------
// Kernel 2 (fused, all-HMMA): i64 x j64 tile, full K=3072.
// 3-stage cp.async pipeline, ONE barrier per BK-32 chunk (safe: the slot
// written at iter c held stage c-1, consumed at iter c-1; the post-wait
// barrier at iter c proves all warps completed iter c-1's compute).
//  S = FQ@FK^T (f32 acc) -> exp2 in regs -> f32 rowsums -> P f16 smem ->
//  O = P @ x_f16 HMMA -> g_acc partial.
// smem 30.7KB (3-stage As/Bs; Ps+xs overlay after mainloop). Grid 256.
// ---------------------------------------------------------------------------
#define SM_BSOFF 15360                    // Bs after As (3*64*40*2)
#define SM_XSOFF 9216                     // xs after Ps (64*72*2)
#define SM_TOT   30720                    // 3-stage As+Bs

__global__ __launch_bounds__(256) void gemm_av_kernel(const float* __restrict__ x) {
    extern __shared__ char dynsm[];
    __half (*As)[64][40] = reinterpret_cast<__half(*)[64][40]>(dynsm);
    __half (*Bs)[64][40] = reinterpret_cast<__half(*)[64][40]>(dynsm + SM_BSOFF);
    __half (*Ps)[72]     = reinterpret_cast<__half(*)[72]>(dynsm);        // overlay
    __half (*xs)[136]    = reinterpret_cast<__half(*)[136]>(dynsm + SM_XSOFF);
    __shared__ float rs[4][64];

    int jb = blockIdx.x;
    int b = blockIdx.z;
    int i0 = blockIdx.y * 64;
    int j0 = jb * 64;
    const __half* FQ = (const __half*)g_FQ4 + ((size_t)b * Lx + i0) * KP;
    const __half* FK = (const __half*)g_FK4 + ((size_t)b * Lx + j0) * KP;

    int tid = threadIdx.x;
    int warp = tid >> 5, lane = tid & 31;
    int wr = warp >> 2, wc = warp & 3;      // 2 x 4

    float acc[2][2][4];
#pragma unroll
    for (int mt = 0; mt < 2; mt++)
#pragma unroll
        for (int nt = 0; nt < 2; nt++)
#pragma unroll
            for (int q = 0; q < 4; q++) acc[mt][nt][q] = 0.f;

    const int NCH = KP / 32;   // 96 chunks
    int row = tid >> 2, seg = tid & 3;

    // prologue: stages 0 and 1
    cp16(saddr(&As[0][row][seg * 8]), FQ + (size_t)row * KP + seg * 8);
    cp16(saddr(&Bs[0][row][seg * 8]), FK + (size_t)row * KP + seg * 8);
    asm volatile("cp.async.commit_group;");
    cp16(saddr(&As[1][row][seg * 8]), FQ + (size_t)row * KP + 32 + seg * 8);
    cp16(saddr(&Bs[1][row][seg * 8]), FK + (size_t)row * KP + 32 + seg * 8);
    asm volatile("cp.async.commit_group;");

    int slot = 0;
    for (int c = 0; c < NCH; c++) {
        if (c + 1 < NCH) {
            asm volatile("cp.async.wait_group 1;");
        } else {
            asm volatile("cp.async.wait_group 0;");
        }
        __syncthreads();

        if (c + 2 < NCH) {
            int co = (c + 2) * 32;
            int ns = (c + 2) % 3;
            cp16(saddr(&As[ns][row][seg * 8]), FQ + (size_t)row * KP + co + seg * 8);
            cp16(saddr(&Bs[ns][row][seg * 8]), FK + (size_t)row * KP + co + seg * 8);
        }
        asm volatile("cp.async.commit_group;");   // uniform group count

#pragma unroll
        for (int ks = 0; ks < 2; ks++) {
            unsigned a[2][4], bb[4];
#pragma unroll
            for (int mt = 0; mt < 2; mt++) {
                int arow = 32 * wr + 16 * mt + (lane & 7) + 8 * ((lane >> 3) & 1);
                int col = ks * 16 + 8 * (lane >> 4);
                ldsm_x4(a[mt][0], a[mt][1], a[mt][2], a[mt][3],
                        saddr(&As[slot][arow][col]));
            }
            {
                int n = 16 * wc + (lane & 7) + 8 * (lane >> 4);
                int col = ks * 16 + 8 * ((lane >> 3) & 1);
                ldsm_x4(bb[0], bb[1], bb[2], bb[3], saddr(&Bs[slot][n][col]));
            }
#pragma unroll
            for (int mt = 0; mt < 2; mt++)
#pragma unroll
                for (int nt = 0; nt < 2; nt++)
                    mma16816(acc[mt][nt], a[mt], bb[2 * nt], bb[2 * nt + 1]);
        }
        slot = (slot == 2) ? 0 : slot + 1;
    }
    __syncthreads();   // all warps done with As/Bs before Ps/xs overlay

    // exp2 + f32 rowsums + P -> f16 smem
    int g = lane >> 2, tg = lane & 3;
    float rsum[4] = {0.f, 0.f, 0.f, 0.f};   // rows 32wr+16mt+{g,g+8}
#pragma unroll
    for (int mt = 0; mt < 2; mt++)
#pragma unroll
        for (int nt = 0; nt < 2; nt++) {
            int r = 32 * wr + 16 * mt + g;
            int n = 16 * wc + 8 * nt + 2 * tg;
            float p0 = ex2_fast(acc[mt][nt][0]);
            float p1 = ex2_fast(acc[mt][nt][1]);
            float p2 = ex2_fast(acc[mt][nt][2]);
            float p3 = ex2_fast(acc[mt][nt][3]);
            rsum[2 * mt + 0] += p0 + p1;
            rsum[2 * mt + 1] += p2 + p3;
            *(__half2*)&Ps[r][n]     = __float22half2_rn(make_float2(p0, p1));
            *(__half2*)&Ps[r + 8][n] = __float22half2_rn(make_float2(p2, p3));
        }
#pragma unroll
    for (int rr = 0; rr < 4; rr++) {
        rsum[rr] += __shfl_xor_sync(0xffffffffu, rsum[rr], 1);
        rsum[rr] += __shfl_xor_sync(0xffffffffu, rsum[rr], 2);
    }
    if (tg == 0) {
#pragma unroll
        for (int mt = 0; mt < 2; mt++) {
            rs[wc][32 * wr + 16 * mt + g]     = rsum[2 * mt + 0];
            rs[wc][32 * wr + 16 * mt + g + 8] = rsum[2 * mt + 1];
        }
    }

    // stage x tile [64 j][128 d] as f16 (L2-hot, 8 float4/thread coalesced)
    {
        const float4* xb4 = (const float4*)(x + ((size_t)b * Lx + j0) * Dx);
#pragma unroll
        for (int t = 0; t < 8; t++) {
            int idx = tid + 256 * t;
            int xrow = idx >> 5, c4 = idx & 31;
            float4 v = xb4[idx];
            *(__half2*)&xs[xrow][4 * c4]     = __float22half2_rn(make_float2(v.x, v.y));
            *(__half2*)&xs[xrow][4 * c4 + 2] = __float22half2_rn(make_float2(v.z, v.w));
        }
    }
    __syncthreads();

    if (tid < 64)
        g_ps[jb][(size_t)b * Lx + i0 + tid] =
            rs[0][tid] + rs[1][tid] + rs[2][tid] + rs[3][tid];

    // AV HMMA: O[64 x 128] = P[64 x 64] @ X[64 x 128]; warp tile m32 x n32
    float acc2[2][4][4];
#pragma unroll
    for (int mt = 0; mt < 2; mt++)
#pragma unroll
        for (int nt = 0; nt < 4; nt++)
#pragma unroll
            for (int q = 0; q < 4; q++) acc2[mt][nt][q] = 0.f;

#pragma unroll
    for (int ks = 0; ks < 4; ks++) {
        unsigned a[2][4], bb2[2][4];
#pragma unroll
        for (int mt = 0; mt < 2; mt++) {
            int prow = 32 * wr + 16 * mt + (lane & 7) + 8 * ((lane >> 3) & 1);
            int col = ks * 16 + 8 * (lane >> 4);
            ldsm_x4(a[mt][0], a[mt][1], a[mt][2], a[mt][3],
                    saddr(&Ps[prow][col]));
        }
#pragma unroll
        for (int nt2 = 0; nt2 < 2; nt2++) {
            int krow = 16 * ks + (lane & 15);
            int ncol = 32 * wc + 16 * nt2 + 8 * (lane >> 4);
            ldsm_x4_t(bb2[nt2][0], bb2[nt2][1], bb2[nt2][2], bb2[nt2][3],
                      saddr(&xs[krow][ncol]));
        }
#pragma unroll
        for (int mt = 0; mt < 2; mt++)
#pragma unroll
            for (int nt = 0; nt < 4; nt++)
                mma16816(acc2[mt][nt], a[mt],
                         bb2[nt >> 1][2 * (nt & 1)], bb2[nt >> 1][2 * (nt & 1) + 1]);
    }

    // write O partial fragments
    float* ga = g_acc[jb] + ((size_t)b * Lx + i0) * Dx;
#pragma unroll
    for (int mt = 0; mt < 2; mt++)
#pragma unroll
        for (int nt = 0; nt < 4; nt++) {
            int r = 32 * wr + 16 * mt + g;
            int dn = 32 * wc + 8 * nt + 2 * tg;
            *(float2*)&ga[(size_t)r * Dx + dn] =
                make_float2(acc2[mt][nt][0], acc2[mt][nt][1]);
            *(float2*)&ga[(size_t)(r + 8) * Dx + dn] =
                make_float2(acc2[mt][nt][2], acc2[mt][nt][3]);
        }
}

// ---------------------------------------------------------------------------
// Kernel 3: combine: out[idx] = sum_jb acc / sum_jb ps.
// ---------------------------------------------------------------------------
__global__ __launch_bounds__(256) void combine_kernel(float* __restrict__ out) {
    int idx = blockIdx.x * 256 + threadIdx.x;   // 0 .. B*L*D-1
    int r = idx >> 7;
    float s = 0.f, v = 0.f;
#pragma unroll
    for (int jb = 0; jb < NJ; jb++) {
        s += g_ps[jb][r];
        v += g_acc[jb][idx];
    }
    out[idx] = v * (1.0f / s);
}

// ---------------------------------------------------------------------------
extern "C" void kernel_launch(void* const* d_in, const int* in_sizes, int n_in,
                              void* d_out, int out_size) {
    const float* x  = (const float*)d_in[0];
    // d_in[1] = mask (bool) — intentionally unused: reference's masked_fill is
    // out-of-place and discarded, so mask has no effect on the output.
    const float* Wq = (const float*)d_in[2];
    const float* bq = (const float*)d_in[3];
    const float* Wk = (const float*)d_in[4];
    const float* bk = (const float*)d_in[5];
    const float* w  = (const float*)d_in[6];
    // d_in[7] = bw — unused: constant score shift cancels in softmax.
    float* out = (float*)d_out;

    dim3 g1(Bx * Lx / 16, 2);
    qkfeat_kernel<<<g1, 256>>>(x, Wq, bq, Wk, bk, w);

    dim3 gg(NJ, Lx / 64, Bx);
    gemm_av_kernel<<<gg, 256, SM_TOT>>>(x);

    combine_kernel<<<Bx * Lx * Dx / 256, 256>>>(out);
}